// round 9
// baseline (speedup 1.0000x reference)
#include <cuda_runtime.h>
#include <cuda_fp16.h>

#define MAXN 100000
#define MAXE 800000

// ---- scratch (device globals; no runtime allocation allowed) ----
__device__ __align__(16) __half g_svh [MAXN * 128];   // [a_src(64)|v(64)] per node
__device__ __align__(16) float  g_denom[MAXN * 64];
__device__ __align__(16) float  g_outh [MAXN * 64];
__device__ int g_cnt [MAXN];      // in-degree
__device__ int g_offp[MAXN];      // per-block exclusive scan
__device__ int g_blk [256];       // block sums
__device__ int g_off [MAXN];      // segment starts
__device__ int g_cur [MAXN];      // scatter cursor
__device__ int g_srcs[MAXE];      // src ids sorted by dst

__device__ __forceinline__ uint2 pack4h(float4 a) {
    uint2 r;
    *(__half2*)&r.x = __float22half2_rn(make_float2(a.x, a.y));
    *(__half2*)&r.y = __float22half2_rn(make_float2(a.z, a.w));
    return r;
}

// ---------------- node projections: a_src & v; self-loop init; zero counts --
// grid: ceil(N/64), block 256; thread = (cg 0..15, ng 0..15) -> 4 nodes x 4 ch
__global__ void __launch_bounds__(256) proj_kernel(
        const float* __restrict__ x,
        const float* __restrict__ Wl,
        const float* __restrict__ Wsrc,
        const float* __restrict__ bpos,
        int N) {
    __shared__ float sWs[64 * 64];
    __shared__ float sWl[64 * 64];
    __shared__ float sx [64 * 68];

    int tid  = threadIdx.x;
    int base = blockIdx.x * 64;

    if (tid < 64 && base + tid < N) g_cnt[base + tid] = 0;

    for (int g = tid; g < 4096; g += 256) {
        int h = g >> 10, k = (g >> 4) & 63, hd = g & 15;
        int o = h * 16 + hd;
        sWs[k * 64 + o] = Wsrc[g];
        sWl[k * 64 + o] = Wl[g];
    }
    for (int i = tid; i < 1024; i += 256) {
        int n = i >> 4, c4 = i & 15;
        int node = base + n;
        float4 xv = (node < N) ? *(const float4*)(x + (size_t)node * 64 + c4 * 4)
                               : make_float4(0.f, 0.f, 0.f, 0.f);
        int c = c4 * 4;
        sx[(c + 0) * 68 + n] = xv.x;
        sx[(c + 1) * 68 + n] = xv.y;
        sx[(c + 2) * 68 + n] = xv.z;
        sx[(c + 3) * 68 + n] = xv.w;
    }
    __syncthreads();

    int cg = tid & 15, ng = tid >> 4;
    float4 accS[4], accV[4];
#pragma unroll
    for (int i = 0; i < 4; i++) {
        accS[i] = make_float4(0.f, 0.f, 0.f, 0.f);
        accV[i] = make_float4(0.f, 0.f, 0.f, 0.f);
    }

#pragma unroll 8
    for (int k = 0; k < 64; k++) {
        float4 ws = *(float4*)(sWs + k * 64 + cg * 4);
        float4 wl = *(float4*)(sWl + k * 64 + cg * 4);
        float4 xa = *(float4*)(sx + k * 68 + ng * 4);
        float xv[4] = {xa.x, xa.y, xa.z, xa.w};
#pragma unroll
        for (int i = 0; i < 4; i++) {
            accS[i].x += xv[i] * ws.x;
            accS[i].y += xv[i] * ws.y;
            accS[i].z += xv[i] * ws.z;
            accS[i].w += xv[i] * ws.w;
            accV[i].x += xv[i] * wl.x;
            accV[i].y += xv[i] * wl.y;
            accV[i].z += xv[i] * wl.z;
            accV[i].w += xv[i] * wl.w;
        }
    }

    float4 b4 = *(const float4*)(bpos + cg * 4);

#pragma unroll
    for (int i = 0; i < 4; i++) {
        int node = base + ng * 4 + i;
        if (node < N) {
            __half* p = g_svh + (size_t)node * 128;
            *(uint2*)(p + cg * 4)      = pack4h(accS[i]);
            *(uint2*)(p + 64 + cg * 4) = pack4h(accV[i]);

            // self-loop: ex = exp(bpos - a_src); outh = ex*(v + bpos)
            float4 ex, m;
            ex.x = __expf(b4.x - accS[i].x);
            ex.y = __expf(b4.y - accS[i].y);
            ex.z = __expf(b4.z - accS[i].z);
            ex.w = __expf(b4.w - accS[i].w);
            m.x = ex.x * (accV[i].x + b4.x);
            m.y = ex.y * (accV[i].y + b4.y);
            m.z = ex.z * (accV[i].z + b4.z);
            m.w = ex.w * (accV[i].w + b4.w);
            *(float4*)(g_denom + (size_t)node * 64 + cg * 4) = ex;
            *(float4*)(g_outh  + (size_t)node * 64 + cg * 4) = m;
        }
    }
}

// ---------------- CSR build ----------------
__global__ void hist_kernel(const int* __restrict__ ei, int E) {
    int e = blockIdx.x * 256 + threadIdx.x;
    if (e < E) atomicAdd(&g_cnt[ei[E + e]], 1);
}

__global__ void scan1_kernel(int n) {
    __shared__ int sh[1024];
    int i = blockIdx.x * 1024 + threadIdx.x;
    int v = (i < n) ? g_cnt[i] : 0;
    sh[threadIdx.x] = v;
    __syncthreads();
#pragma unroll
    for (int off = 1; off < 1024; off <<= 1) {
        int t = (threadIdx.x >= off) ? sh[threadIdx.x - off] : 0;
        __syncthreads();
        sh[threadIdx.x] += t;
        __syncthreads();
    }
    if (i < n) g_offp[i] = sh[threadIdx.x] - v;   // exclusive
    if (threadIdx.x == 1023) g_blk[blockIdx.x] = sh[1023];
}

__global__ void scan2_kernel(int nb) {
    if (threadIdx.x == 0) {
        int run = 0;
        for (int b = 0; b < nb; b++) { int t = g_blk[b]; g_blk[b] = run; run += t; }
    }
}

__global__ void scan3_kernel(int n) {
    int i = blockIdx.x * 1024 + threadIdx.x;
    if (i < n) {
        int o = g_offp[i] + g_blk[i >> 10];
        g_off[i] = o;
        g_cur[i] = o;
    }
}

__global__ void scatter_kernel(const int* __restrict__ ei, int E) {
    int e = blockIdx.x * 256 + threadIdx.x;
    if (e < E) {
        int d = ei[E + e];
        int idx = atomicAdd(&g_cur[d], 1);
        g_srcs[idx] = ei[e];
    }
}

// ---------------- aggregate: one warp per destination node ----------------
// lane handles channels (2*lane, 2*lane+1); accumulates denom/outh in regs.
__global__ void __launch_bounds__(256) aggregate_kernel(
        const float* __restrict__ pos,
        const float* __restrict__ Wpos,
        const float* __restrict__ bpos,
        int N) {
    int d    = (blockIdx.x * 256 + threadIdx.x) >> 5;
    int lane = threadIdx.x & 31;
    if (d >= N) return;

    int c0 = lane * 2;
    int h = c0 >> 4, hd = c0 & 15;
    float2 wx = *(const float2*)(Wpos + h * 48 + hd);
    float2 wy = *(const float2*)(Wpos + h * 48 + 16 + hd);
    float2 wz = *(const float2*)(Wpos + h * 48 + 32 + hd);
    float2 bb = *(const float2*)(bpos + h * 16 + hd);

    float pdx = pos[d * 3 + 0];
    float pdy = pos[d * 3 + 1];
    float pdz = pos[d * 3 + 2];

    int start = g_off[d];
    int cnt   = g_cnt[d];

    // seed with self-loop contribution written by proj
    float2 accD = *(float2*)(g_denom + (size_t)d * 64 + c0);
    float2 accM = *(float2*)(g_outh  + (size_t)d * 64 + c0);

#pragma unroll 2
    for (int i = 0; i < cnt; i++) {
        int s = g_srcs[start + i];
        float rx = pdx - pos[s * 3 + 0];
        float ry = pdy - pos[s * 3 + 1];
        float rz = pdz - pos[s * 3 + 2];
        float dlx = bb.x + rx * wx.x + ry * wy.x + rz * wz.x;
        float dly = bb.y + rx * wx.y + ry * wy.y + rz * wz.y;

        const __half* p = g_svh + (size_t)s * 128;
        float2 a = __half22float2(*(const __half2*)(p + c0));
        float2 v = __half22float2(*(const __half2*)(p + 64 + c0));

        float ex0 = __expf(dlx - a.x);
        float ex1 = __expf(dly - a.y);
        accD.x += ex0;
        accD.y += ex1;
        accM.x += ex0 * (v.x + dlx);
        accM.y += ex1 * (v.y + dly);
    }

    *(float2*)(g_denom + (size_t)d * 64 + c0) = accD;
    *(float2*)(g_outh  + (size_t)d * 64 + c0) = accM;
}

// ---------------- MLP: t = outh/denom; y = relu(t@W1+b1)@W2+b2 ----------------
__global__ void __launch_bounds__(256) mlp_kernel(
        const float* __restrict__ W1,
        const float* __restrict__ b1,
        const float* __restrict__ W2,
        const float* __restrict__ b2,
        float* __restrict__ out, int N) {
    __shared__ float sW1[64 * 64];
    __shared__ float sW2[64 * 64];
    __shared__ float sx [64 * 68];
    int tid  = threadIdx.x;
    int base = blockIdx.x * 64;

    for (int g = tid; g < 4096; g += 256) { sW1[g] = W1[g]; sW2[g] = W2[g]; }

    for (int i = tid; i < 1024; i += 256) {
        int n = i >> 4, c4 = i & 15;
        int node = base + n;
        float4 o4 = make_float4(0.f, 0.f, 0.f, 0.f);
        float4 d4 = make_float4(1.f, 1.f, 1.f, 1.f);
        if (node < N) {
            o4 = ((const float4*)g_outh)[(size_t)node * 16 + c4];
            d4 = ((const float4*)g_denom)[(size_t)node * 16 + c4];
        }
        int c = c4 * 4;
        sx[(c + 0) * 68 + n] = o4.x / d4.x;
        sx[(c + 1) * 68 + n] = o4.y / d4.y;
        sx[(c + 2) * 68 + n] = o4.z / d4.z;
        sx[(c + 3) * 68 + n] = o4.w / d4.w;
    }
    __syncthreads();

    int cg = tid & 15, ng = tid >> 4;
    float4 bias = *(const float4*)(b1 + cg * 4);
    float4 acc[4];
#pragma unroll
    for (int i = 0; i < 4; i++) acc[i] = bias;

#pragma unroll 8
    for (int k = 0; k < 64; k++) {
        float4 w  = *(float4*)(sW1 + k * 64 + cg * 4);
        float4 xa = *(float4*)(sx + k * 68 + ng * 4);
        float xv[4] = {xa.x, xa.y, xa.z, xa.w};
#pragma unroll
        for (int i = 0; i < 4; i++) {
            acc[i].x += xv[i] * w.x;
            acc[i].y += xv[i] * w.y;
            acc[i].z += xv[i] * w.z;
            acc[i].w += xv[i] * w.w;
        }
    }
    __syncthreads();

#pragma unroll
    for (int i = 0; i < 4; i++) {
        int n = ng * 4 + i;
        sx[(cg * 4 + 0) * 68 + n] = fmaxf(acc[i].x, 0.f);
        sx[(cg * 4 + 1) * 68 + n] = fmaxf(acc[i].y, 0.f);
        sx[(cg * 4 + 2) * 68 + n] = fmaxf(acc[i].z, 0.f);
        sx[(cg * 4 + 3) * 68 + n] = fmaxf(acc[i].w, 0.f);
    }
    __syncthreads();

    float4 bias2 = *(const float4*)(b2 + cg * 4);
#pragma unroll
    for (int i = 0; i < 4; i++) acc[i] = bias2;

#pragma unroll 8
    for (int k = 0; k < 64; k++) {
        float4 w  = *(float4*)(sW2 + k * 64 + cg * 4);
        float4 xa = *(float4*)(sx + k * 68 + ng * 4);
        float xv[4] = {xa.x, xa.y, xa.z, xa.w};
#pragma unroll
        for (int i = 0; i < 4; i++) {
            acc[i].x += xv[i] * w.x;
            acc[i].y += xv[i] * w.y;
            acc[i].z += xv[i] * w.z;
            acc[i].w += xv[i] * w.w;
        }
    }
#pragma unroll
    for (int i = 0; i < 4; i++) {
        int node = base + ng * 4 + i;
        if (node < N)
            *(float4*)(out + (size_t)node * 64 + cg * 4) = acc[i];
    }
}

extern "C" void kernel_launch(void* const* d_in, const int* in_sizes, int n_in,
                              void* d_out, int out_size) {
    const float* x    = (const float*)d_in[0];
    const float* pos  = (const float*)d_in[1];
    const int*   ei   = (const int*)d_in[2];
    const float* Wl   = (const float*)d_in[3];
    const float* Wsrc = (const float*)d_in[4];
    // d_in[5] = W_dst  (unused: cancels exactly in the segment softmax)
    const float* Wpos = (const float*)d_in[6];
    const float* bpos = (const float*)d_in[7];
    const float* W1   = (const float*)d_in[8];
    const float* b1   = (const float*)d_in[9];
    const float* W2   = (const float*)d_in[10];
    const float* b2   = (const float*)d_in[11];
    float* out = (float*)d_out;

    int N  = in_sizes[0] / 64;
    int E  = in_sizes[2] / 2;

    proj_kernel<<<(N + 63) / 64, 256>>>(x, Wl, Wsrc, bpos, N);

    int egrid = (E + 255) / 256;
    hist_kernel<<<egrid, 256>>>(ei, E);

    int nscan = (N + 1023) / 1024;
    scan1_kernel<<<nscan, 1024>>>(N);
    scan2_kernel<<<1, 32>>>(nscan);
    scan3_kernel<<<nscan, 1024>>>(N);

    scatter_kernel<<<egrid, 256>>>(ei, E);

    aggregate_kernel<<<(N * 32 + 255) / 256, 256>>>(pos, Wpos, bpos, N);

    mlp_kernel<<<(N + 63) / 64, 256>>>(W1, b1, W2, b2, out, N);
}

// round 10
// speedup vs baseline: 1.0470x; 1.0470x over previous
#include <cuda_runtime.h>
#include <cuda_fp16.h>

#define MAXN 100000
#define MAXE 800000

// ---- scratch (device globals; no runtime allocation allowed) ----
// g_svh: per node 128 halves, channel-interleaved: [a0,v0,a1,v1,...,a63,v63]
__device__ __align__(16) __half g_svh [MAXN * 128];
__device__ __align__(16) float  g_denom[MAXN * 64];
__device__ __align__(16) float  g_outh [MAXN * 64];
__device__ __align__(16) float4 g_pos4[MAXN];
__device__ int g_cnt [MAXN];      // in-degree
__device__ int g_offp[MAXN];      // per-block exclusive scan
__device__ int g_blk [128];       // block sums
__device__ int g_off [MAXN];      // segment starts (advanced to end by scatter)
__device__ int g_srcs[MAXE];      // src ids grouped by dst

// ---------------- node projections: a_src & v; self-loop init; misc init ----
// grid: ceil(N/64), block 256; thread = (cg 0..15, ng 0..15) -> 4 nodes x 4 ch
__global__ void __launch_bounds__(256) proj_kernel(
        const float* __restrict__ x,
        const float* __restrict__ pos,
        const float* __restrict__ Wl,
        const float* __restrict__ Wsrc,
        const float* __restrict__ bpos,
        int N) {
    __shared__ float sWs[64 * 64];
    __shared__ float sWl[64 * 64];
    __shared__ float sx [64 * 68];

    int tid  = threadIdx.x;
    int base = blockIdx.x * 64;

    if (tid < 64) {
        int node = base + tid;
        if (node < N) {
            g_cnt[node] = 0;
            g_pos4[node] = make_float4(pos[node * 3 + 0], pos[node * 3 + 1],
                                       pos[node * 3 + 2], 0.f);
        }
    }

    for (int g = tid; g < 4096; g += 256) {
        int h = g >> 10, k = (g >> 4) & 63, hd = g & 15;
        int o = h * 16 + hd;
        sWs[k * 64 + o] = Wsrc[g];
        sWl[k * 64 + o] = Wl[g];
    }
    for (int i = tid; i < 1024; i += 256) {
        int n = i >> 4, c4 = i & 15;
        int node = base + n;
        float4 xv = (node < N) ? *(const float4*)(x + (size_t)node * 64 + c4 * 4)
                               : make_float4(0.f, 0.f, 0.f, 0.f);
        int c = c4 * 4;
        sx[(c + 0) * 68 + n] = xv.x;
        sx[(c + 1) * 68 + n] = xv.y;
        sx[(c + 2) * 68 + n] = xv.z;
        sx[(c + 3) * 68 + n] = xv.w;
    }
    __syncthreads();

    int cg = tid & 15, ng = tid >> 4;
    float4 accS[4], accV[4];
#pragma unroll
    for (int i = 0; i < 4; i++) {
        accS[i] = make_float4(0.f, 0.f, 0.f, 0.f);
        accV[i] = make_float4(0.f, 0.f, 0.f, 0.f);
    }

#pragma unroll 8
    for (int k = 0; k < 64; k++) {
        float4 ws = *(float4*)(sWs + k * 64 + cg * 4);
        float4 wl = *(float4*)(sWl + k * 64 + cg * 4);
        float4 xa = *(float4*)(sx + k * 68 + ng * 4);
        float xv[4] = {xa.x, xa.y, xa.z, xa.w};
#pragma unroll
        for (int i = 0; i < 4; i++) {
            accS[i].x += xv[i] * ws.x;
            accS[i].y += xv[i] * ws.y;
            accS[i].z += xv[i] * ws.z;
            accS[i].w += xv[i] * ws.w;
            accV[i].x += xv[i] * wl.x;
            accV[i].y += xv[i] * wl.y;
            accV[i].z += xv[i] * wl.z;
            accV[i].w += xv[i] * wl.w;
        }
    }

    float4 b4 = *(const float4*)(bpos + cg * 4);

#pragma unroll
    for (int i = 0; i < 4; i++) {
        int node = base + ng * 4 + i;
        if (node < N) {
            // channel-interleaved fp16 store: {a_c,v_c} pairs, 16B per thread
            uint4 o;
            *(__half2*)&o.x = __float22half2_rn(make_float2(accS[i].x, accV[i].x));
            *(__half2*)&o.y = __float22half2_rn(make_float2(accS[i].y, accV[i].y));
            *(__half2*)&o.z = __float22half2_rn(make_float2(accS[i].z, accV[i].z));
            *(__half2*)&o.w = __float22half2_rn(make_float2(accS[i].w, accV[i].w));
            *(uint4*)(g_svh + (size_t)node * 128 + cg * 8) = o;

            // self-loop: ex = exp(bpos - a_src); outh = ex*(v + bpos)
            float4 ex, m;
            ex.x = __expf(b4.x - accS[i].x);
            ex.y = __expf(b4.y - accS[i].y);
            ex.z = __expf(b4.z - accS[i].z);
            ex.w = __expf(b4.w - accS[i].w);
            m.x = ex.x * (accV[i].x + b4.x);
            m.y = ex.y * (accV[i].y + b4.y);
            m.z = ex.z * (accV[i].z + b4.z);
            m.w = ex.w * (accV[i].w + b4.w);
            *(float4*)(g_denom + (size_t)node * 64 + cg * 4) = ex;
            *(float4*)(g_outh  + (size_t)node * 64 + cg * 4) = m;
        }
    }
}

// ---------------- CSR build ----------------
__global__ void hist_kernel(const int* __restrict__ ei, int E) {
    int e = blockIdx.x * 256 + threadIdx.x;
    if (e < E) atomicAdd(&g_cnt[ei[E + e]], 1);
}

// warp-shuffle scan over 1024 elements per block
__global__ void scan1_kernel(int n) {
    __shared__ int ws[32];
    int i = blockIdx.x * 1024 + threadIdx.x;
    int v = (i < n) ? g_cnt[i] : 0;
    int lane = threadIdx.x & 31, w = threadIdx.x >> 5;
    int xi = v;
#pragma unroll
    for (int o = 1; o < 32; o <<= 1) {
        int t = __shfl_up_sync(~0u, xi, o);
        if (lane >= o) xi += t;
    }
    if (lane == 31) ws[w] = xi;
    __syncthreads();
    if (w == 0) {
        int y = ws[lane];
#pragma unroll
        for (int o = 1; o < 32; o <<= 1) {
            int t = __shfl_up_sync(~0u, y, o);
            if (lane >= o) y += t;
        }
        ws[lane] = y;
    }
    __syncthreads();
    int pre = (w > 0 ? ws[w - 1] : 0) + xi - v;   // exclusive
    if (i < n) g_offp[i] = pre;
    if (threadIdx.x == 1023) g_blk[blockIdx.x] = pre + v;
}

// scan over <=128 block sums, 1 block of 128 threads
__global__ void scan2_kernel(int nb) {
    __shared__ int ws[4];
    int tid = threadIdx.x;
    int v = (tid < nb) ? g_blk[tid] : 0;
    int lane = tid & 31, w = tid >> 5;
    int xi = v;
#pragma unroll
    for (int o = 1; o < 32; o <<= 1) {
        int t = __shfl_up_sync(~0u, xi, o);
        if (lane >= o) xi += t;
    }
    if (lane == 31) ws[w] = xi;
    __syncthreads();
    int add = 0;
#pragma unroll
    for (int k = 0; k < 4; k++) add += (k < w) ? ws[k] : 0;
    if (tid < nb) g_blk[tid] = add + xi - v;   // exclusive
}

__global__ void scan3_kernel(int n) {
    int i = blockIdx.x * 1024 + threadIdx.x;
    if (i < n) g_off[i] = g_offp[i] + g_blk[i >> 10];
}

__global__ void scatter_kernel(const int* __restrict__ ei, int E) {
    int e = blockIdx.x * 256 + threadIdx.x;
    if (e < E) {
        int d = ei[E + e];
        int idx = atomicAdd(&g_off[d], 1);   // g_off ends at segment end
        g_srcs[idx] = ei[e];
    }
}

// ---------------- aggregate: one warp per destination node ----------------
// lane handles channels (2*lane, 2*lane+1); per edge: 1 srcs + 1 pos4 + 1 sv LDG.
__global__ void __launch_bounds__(256) aggregate_kernel(
        const float* __restrict__ Wpos,
        const float* __restrict__ bpos,
        int N) {
    int d    = (blockIdx.x * 256 + threadIdx.x) >> 5;
    int lane = threadIdx.x & 31;
    if (d >= N) return;

    int c0 = lane * 2;
    int h = c0 >> 4, hd = c0 & 15;
    float2 wx = *(const float2*)(Wpos + h * 48 + hd);
    float2 wy = *(const float2*)(Wpos + h * 48 + 16 + hd);
    float2 wz = *(const float2*)(Wpos + h * 48 + 32 + hd);
    float2 bb = *(const float2*)(bpos + h * 16 + hd);

    float4 pd = g_pos4[d];
    int end   = g_off[d];        // advanced to end by scatter
    int cnt   = g_cnt[d];
    int start = end - cnt;

    // seed with self-loop contribution written by proj
    float2 accD = *(float2*)(g_denom + (size_t)d * 64 + c0);
    float2 accM = *(float2*)(g_outh  + (size_t)d * 64 + c0);

    int i = 0;
    for (; i + 2 <= cnt; i += 2) {
        int s0 = g_srcs[start + i];
        int s1 = g_srcs[start + i + 1];
        float4 p0 = g_pos4[s0];
        float4 p1 = g_pos4[s1];
        uint2 u0 = *(const uint2*)(g_svh + (size_t)s0 * 128 + c0 * 2);
        uint2 u1 = *(const uint2*)(g_svh + (size_t)s1 * 128 + c0 * 2);

        float rx0 = pd.x - p0.x, ry0 = pd.y - p0.y, rz0 = pd.z - p0.z;
        float rx1 = pd.x - p1.x, ry1 = pd.y - p1.y, rz1 = pd.z - p1.z;
        float dlx0 = bb.x + rx0 * wx.x + ry0 * wy.x + rz0 * wz.x;
        float dly0 = bb.y + rx0 * wx.y + ry0 * wy.y + rz0 * wz.y;
        float dlx1 = bb.x + rx1 * wx.x + ry1 * wy.x + rz1 * wz.x;
        float dly1 = bb.y + rx1 * wx.y + ry1 * wy.y + rz1 * wz.y;

        float2 q00 = __half22float2(*(__half2*)&u0.x);  // a(c0), v(c0)
        float2 q01 = __half22float2(*(__half2*)&u0.y);  // a(c1), v(c1)
        float2 q10 = __half22float2(*(__half2*)&u1.x);
        float2 q11 = __half22float2(*(__half2*)&u1.y);

        float e00 = __expf(dlx0 - q00.x);
        float e01 = __expf(dly0 - q01.x);
        float e10 = __expf(dlx1 - q10.x);
        float e11 = __expf(dly1 - q11.x);
        accD.x += e00 + e10;
        accD.y += e01 + e11;
        accM.x += e00 * (q00.y + dlx0) + e10 * (q10.y + dlx1);
        accM.y += e01 * (q01.y + dly0) + e11 * (q11.y + dly1);
    }
    if (i < cnt) {
        int s0 = g_srcs[start + i];
        float4 p0 = g_pos4[s0];
        uint2 u0 = *(const uint2*)(g_svh + (size_t)s0 * 128 + c0 * 2);
        float rx0 = pd.x - p0.x, ry0 = pd.y - p0.y, rz0 = pd.z - p0.z;
        float dlx0 = bb.x + rx0 * wx.x + ry0 * wy.x + rz0 * wz.x;
        float dly0 = bb.y + rx0 * wx.y + ry0 * wy.y + rz0 * wz.y;
        float2 q00 = __half22float2(*(__half2*)&u0.x);
        float2 q01 = __half22float2(*(__half2*)&u0.y);
        float e00 = __expf(dlx0 - q00.x);
        float e01 = __expf(dly0 - q01.x);
        accD.x += e00;
        accD.y += e01;
        accM.x += e00 * (q00.y + dlx0);
        accM.y += e01 * (q01.y + dly0);
    }

    *(float2*)(g_denom + (size_t)d * 64 + c0) = accD;
    *(float2*)(g_outh  + (size_t)d * 64 + c0) = accM;
}

// ---------------- MLP: t = outh/denom; y = relu(t@W1+b1)@W2+b2 ----------------
__global__ void __launch_bounds__(256) mlp_kernel(
        const float* __restrict__ W1,
        const float* __restrict__ b1,
        const float* __restrict__ W2,
        const float* __restrict__ b2,
        float* __restrict__ out, int N) {
    __shared__ float sW1[64 * 64];
    __shared__ float sW2[64 * 64];
    __shared__ float sx [64 * 68];
    int tid  = threadIdx.x;
    int base = blockIdx.x * 64;

    for (int g = tid; g < 4096; g += 256) { sW1[g] = W1[g]; sW2[g] = W2[g]; }

    for (int i = tid; i < 1024; i += 256) {
        int n = i >> 4, c4 = i & 15;
        int node = base + n;
        float4 o4 = make_float4(0.f, 0.f, 0.f, 0.f);
        float4 d4 = make_float4(1.f, 1.f, 1.f, 1.f);
        if (node < N) {
            o4 = ((const float4*)g_outh)[(size_t)node * 16 + c4];
            d4 = ((const float4*)g_denom)[(size_t)node * 16 + c4];
        }
        int c = c4 * 4;
        sx[(c + 0) * 68 + n] = o4.x / d4.x;
        sx[(c + 1) * 68 + n] = o4.y / d4.y;
        sx[(c + 2) * 68 + n] = o4.z / d4.z;
        sx[(c + 3) * 68 + n] = o4.w / d4.w;
    }
    __syncthreads();

    int cg = tid & 15, ng = tid >> 4;
    float4 bias = *(const float4*)(b1 + cg * 4);
    float4 acc[4];
#pragma unroll
    for (int i = 0; i < 4; i++) acc[i] = bias;

#pragma unroll 8
    for (int k = 0; k < 64; k++) {
        float4 w  = *(float4*)(sW1 + k * 64 + cg * 4);
        float4 xa = *(float4*)(sx + k * 68 + ng * 4);
        float xv[4] = {xa.x, xa.y, xa.z, xa.w};
#pragma unroll
        for (int i = 0; i < 4; i++) {
            acc[i].x += xv[i] * w.x;
            acc[i].y += xv[i] * w.y;
            acc[i].z += xv[i] * w.z;
            acc[i].w += xv[i] * w.w;
        }
    }
    __syncthreads();

#pragma unroll
    for (int i = 0; i < 4; i++) {
        int n = ng * 4 + i;
        sx[(cg * 4 + 0) * 68 + n] = fmaxf(acc[i].x, 0.f);
        sx[(cg * 4 + 1) * 68 + n] = fmaxf(acc[i].y, 0.f);
        sx[(cg * 4 + 2) * 68 + n] = fmaxf(acc[i].z, 0.f);
        sx[(cg * 4 + 3) * 68 + n] = fmaxf(acc[i].w, 0.f);
    }
    __syncthreads();

    float4 bias2 = *(const float4*)(b2 + cg * 4);
#pragma unroll
    for (int i = 0; i < 4; i++) acc[i] = bias2;

#pragma unroll 8
    for (int k = 0; k < 64; k++) {
        float4 w  = *(float4*)(sW2 + k * 64 + cg * 4);
        float4 xa = *(float4*)(sx + k * 68 + ng * 4);
        float xv[4] = {xa.x, xa.y, xa.z, xa.w};
#pragma unroll
        for (int i = 0; i < 4; i++) {
            acc[i].x += xv[i] * w.x;
            acc[i].y += xv[i] * w.y;
            acc[i].z += xv[i] * w.z;
            acc[i].w += xv[i] * w.w;
        }
    }
#pragma unroll
    for (int i = 0; i < 4; i++) {
        int node = base + ng * 4 + i;
        if (node < N)
            *(float4*)(out + (size_t)node * 64 + cg * 4) = acc[i];
    }
}

extern "C" void kernel_launch(void* const* d_in, const int* in_sizes, int n_in,
                              void* d_out, int out_size) {
    const float* x    = (const float*)d_in[0];
    const float* pos  = (const float*)d_in[1];
    const int*   ei   = (const int*)d_in[2];
    const float* Wl   = (const float*)d_in[3];
    const float* Wsrc = (const float*)d_in[4];
    // d_in[5] = W_dst  (unused: cancels exactly in the segment softmax)
    const float* Wpos = (const float*)d_in[6];
    const float* bpos = (const float*)d_in[7];
    const float* W1   = (const float*)d_in[8];
    const float* b1   = (const float*)d_in[9];
    const float* W2   = (const float*)d_in[10];
    const float* b2   = (const float*)d_in[11];
    float* out = (float*)d_out;

    int N  = in_sizes[0] / 64;
    int E  = in_sizes[2] / 2;

    proj_kernel<<<(N + 63) / 64, 256>>>(x, pos, Wl, Wsrc, bpos, N);

    int egrid = (E + 255) / 256;
    hist_kernel<<<egrid, 256>>>(ei, E);

    int nscan = (N + 1023) / 1024;
    scan1_kernel<<<nscan, 1024>>>(N);
    scan2_kernel<<<1, 128>>>(nscan);
    scan3_kernel<<<nscan, 1024>>>(N);

    scatter_kernel<<<egrid, 256>>>(ei, E);

    aggregate_kernel<<<(N * 32 + 255) / 256, 256>>>(Wpos, bpos, N);

    mlp_kernel<<<(N + 63) / 64, 256>>>(W1, b1, W2, b2, out, N);
}

// round 11
// speedup vs baseline: 1.1001x; 1.0508x over previous
#include <cuda_runtime.h>
#include <cuda_fp16.h>

#define MAXN 100000
#define MAXE 800000

// ---- scratch (device globals; no runtime allocation allowed) ----
// g_svh: per node 128 halves, channel-interleaved: [a0,v0,a1,v1,...,a63,v63]
__device__ __align__(16) __half g_svh [MAXN * 128];
__device__ __align__(16) float  g_denom[MAXN * 64];
__device__ __align__(16) float  g_outh [MAXN * 64];
__device__ __align__(16) float4 g_pos4[MAXN];
__device__ int g_cnt [MAXN];      // in-degree (left ZERO by aggregate for next call)
__device__ int g_off [MAXN];      // segment starts (advanced to end by scatter)
__device__ int g_srcs[MAXE];      // src ids grouped by dst
__device__ int g_total;           // bump allocator (left ZERO by proj for next call)

// ---- packed f32x2 helpers (sm_103a dual-issue float pipe) ----
union F2U { float2 f; unsigned long long u; };
__device__ __forceinline__ float2 ffma2(float2 a, float2 b, float2 c) {
    F2U A, B, C, D; A.f = a; B.f = b; C.f = c;
    asm("fma.rn.f32x2 %0, %1, %2, %3;" : "=l"(D.u) : "l"(A.u), "l"(B.u), "l"(C.u));
    return D.f;
}
__device__ __forceinline__ float2 fadd2(float2 a, float2 b) {
    F2U A, B, D; A.f = a; B.f = b;
    asm("add.rn.f32x2 %0, %1, %2;" : "=l"(D.u) : "l"(A.u), "l"(B.u));
    return D.f;
}

// ---------------- proj (+ fused hist in extra blocks) ----------------
// node blocks: a_src & v GEMMs, self-loop init, pos4 build
// edge blocks (blockIdx.x >= nodeBlocks): histogram g_cnt[dst]++
__global__ void __launch_bounds__(256) proj_kernel(
        const float* __restrict__ x,
        const float* __restrict__ pos,
        const int*   __restrict__ ei,
        const float* __restrict__ Wl,
        const float* __restrict__ Wsrc,
        const float* __restrict__ bpos,
        int N, int E, int nodeBlocks) {
    if ((int)blockIdx.x >= nodeBlocks) {
        // ---- histogram blocks: 4 edges per thread ----
        int eb = blockIdx.x - nodeBlocks;
        int e0 = eb * 1024 + threadIdx.x;
#pragma unroll
        for (int k = 0; k < 4; k++) {
            int e = e0 + k * 256;
            if (e < E) atomicAdd(&g_cnt[ei[E + e]], 1);
        }
        return;
    }

    __shared__ float sWs[64 * 64];
    __shared__ float sWl[64 * 64];
    __shared__ float sx [64 * 68];

    int tid  = threadIdx.x;
    int base = blockIdx.x * 64;

    if (blockIdx.x == 0 && tid == 0) g_total = 0;
    if (tid < 64) {
        int node = base + tid;
        if (node < N)
            g_pos4[node] = make_float4(pos[node * 3 + 0], pos[node * 3 + 1],
                                       pos[node * 3 + 2], 0.f);
    }

    for (int g = tid; g < 4096; g += 256) {
        int h = g >> 10, k = (g >> 4) & 63, hd = g & 15;
        int o = h * 16 + hd;
        sWs[k * 64 + o] = Wsrc[g];
        sWl[k * 64 + o] = Wl[g];
    }
    for (int i = tid; i < 1024; i += 256) {
        int n = i >> 4, c4 = i & 15;
        int node = base + n;
        float4 xv = (node < N) ? *(const float4*)(x + (size_t)node * 64 + c4 * 4)
                               : make_float4(0.f, 0.f, 0.f, 0.f);
        int c = c4 * 4;
        sx[(c + 0) * 68 + n] = xv.x;
        sx[(c + 1) * 68 + n] = xv.y;
        sx[(c + 2) * 68 + n] = xv.z;
        sx[(c + 3) * 68 + n] = xv.w;
    }
    __syncthreads();

    int cg = tid & 15, ng = tid >> 4;
    float4 accS[4], accV[4];
#pragma unroll
    for (int i = 0; i < 4; i++) {
        accS[i] = make_float4(0.f, 0.f, 0.f, 0.f);
        accV[i] = make_float4(0.f, 0.f, 0.f, 0.f);
    }

#pragma unroll 8
    for (int k = 0; k < 64; k++) {
        float4 ws = *(float4*)(sWs + k * 64 + cg * 4);
        float4 wl = *(float4*)(sWl + k * 64 + cg * 4);
        float4 xa = *(float4*)(sx + k * 68 + ng * 4);
        float xv[4] = {xa.x, xa.y, xa.z, xa.w};
#pragma unroll
        for (int i = 0; i < 4; i++) {
            accS[i].x += xv[i] * ws.x;
            accS[i].y += xv[i] * ws.y;
            accS[i].z += xv[i] * ws.z;
            accS[i].w += xv[i] * ws.w;
            accV[i].x += xv[i] * wl.x;
            accV[i].y += xv[i] * wl.y;
            accV[i].z += xv[i] * wl.z;
            accV[i].w += xv[i] * wl.w;
        }
    }

    float4 b4 = *(const float4*)(bpos + cg * 4);

#pragma unroll
    for (int i = 0; i < 4; i++) {
        int node = base + ng * 4 + i;
        if (node < N) {
            // channel-interleaved fp16 store: {a_c,v_c} pairs
            uint4 o;
            *(__half2*)&o.x = __float22half2_rn(make_float2(accS[i].x, accV[i].x));
            *(__half2*)&o.y = __float22half2_rn(make_float2(accS[i].y, accV[i].y));
            *(__half2*)&o.z = __float22half2_rn(make_float2(accS[i].z, accV[i].z));
            *(__half2*)&o.w = __float22half2_rn(make_float2(accS[i].w, accV[i].w));
            *(uint4*)(g_svh + (size_t)node * 128 + cg * 8) = o;

            // self-loop: ex = exp(bpos - a_src); outh = ex*(v + bpos)
            float4 ex, m;
            ex.x = __expf(b4.x - accS[i].x);
            ex.y = __expf(b4.y - accS[i].y);
            ex.z = __expf(b4.z - accS[i].z);
            ex.w = __expf(b4.w - accS[i].w);
            m.x = ex.x * (accV[i].x + b4.x);
            m.y = ex.y * (accV[i].y + b4.y);
            m.z = ex.z * (accV[i].z + b4.z);
            m.w = ex.w * (accV[i].w + b4.w);
            *(float4*)(g_denom + (size_t)node * 64 + cg * 4) = ex;
            *(float4*)(g_outh  + (size_t)node * 64 + cg * 4) = m;
        }
    }
}

// ---------------- one-kernel segment allocation (atomic-bump scan) ----------
// 1024 threads/block (32 warps). Block-local exclusive scan of g_cnt, block
// base from atomicAdd(g_total). Segment ordering varies run-to-run but is
// consistent within one call (only fp summation order is affected).
__global__ void alloc_kernel(int n) {
    __shared__ int ws[32];
    __shared__ int sbase;
    int i = blockIdx.x * 1024 + threadIdx.x;
    int v = (i < n) ? g_cnt[i] : 0;
    int lane = threadIdx.x & 31, w = threadIdx.x >> 5;
    int xi = v;
#pragma unroll
    for (int o = 1; o < 32; o <<= 1) {
        int t = __shfl_up_sync(~0u, xi, o);
        if (lane >= o) xi += t;
    }
    if (lane == 31) ws[w] = xi;
    __syncthreads();
    if (w == 0) {
        int y = ws[lane];
#pragma unroll
        for (int o = 1; o < 32; o <<= 1) {
            int t = __shfl_up_sync(~0u, y, o);
            if (lane >= o) y += t;
        }
        ws[lane] = y;
    }
    __syncthreads();
    if (threadIdx.x == 0) sbase = atomicAdd(&g_total, ws[31]);
    __syncthreads();
    if (i < n) g_off[i] = sbase + (w > 0 ? ws[w - 1] : 0) + xi - v;  // exclusive
}

__global__ void scatter_kernel(const int* __restrict__ ei, int E) {
    int e = blockIdx.x * 256 + threadIdx.x;
    if (e < E) {
        int d = ei[E + e];
        int idx = atomicAdd(&g_off[d], 1);   // g_off ends at segment end
        g_srcs[idx] = ei[e];
    }
}

// ---------------- aggregate: one warp per destination node ----------------
__device__ __forceinline__ void edge_acc(
        const float4& pd, const float4& ps, uint2 u,
        const float2& wx, const float2& wy, const float2& wz, const float2& bb,
        float2& accD, float2& accM) {
    float rx = pd.x - ps.x, ry = pd.y - ps.y, rz = pd.z - ps.z;
    float2 dl = ffma2(make_float2(rx, rx), wx,
                ffma2(make_float2(ry, ry), wy,
                ffma2(make_float2(rz, rz), wz, bb)));
    float2 q0 = __half22float2(*(__half2*)&u.x);   // (a_c0, v_c0)
    float2 q1 = __half22float2(*(__half2*)&u.y);   // (a_c1, v_c1)
    float2 ex = make_float2(__expf(dl.x - q0.x), __expf(dl.y - q1.x));
    float2 vv = make_float2(q0.y, q1.y);
    accD = fadd2(accD, ex);
    accM = ffma2(ex, fadd2(vv, dl), accM);
}

__global__ void __launch_bounds__(256) aggregate_kernel(
        const float* __restrict__ Wpos,
        const float* __restrict__ bpos,
        int N) {
    int d    = (blockIdx.x * 256 + threadIdx.x) >> 5;
    int lane = threadIdx.x & 31;
    if (d >= N) return;

    int c0 = lane * 2;
    int h = c0 >> 4, hd = c0 & 15;
    float2 wx = *(const float2*)(Wpos + h * 48 + hd);
    float2 wy = *(const float2*)(Wpos + h * 48 + 16 + hd);
    float2 wz = *(const float2*)(Wpos + h * 48 + 32 + hd);
    float2 bb = *(const float2*)(bpos + h * 16 + hd);

    float4 pd = g_pos4[d];
    int end   = g_off[d];        // advanced to end by scatter
    int cnt   = g_cnt[d];
    int start = end - cnt;
    if (lane == 0) g_cnt[d] = 0;     // self-clean for the next call's histogram

    // seed with self-loop contribution written by proj
    float2 accD = *(float2*)(g_denom + (size_t)d * 64 + c0);
    float2 accM = *(float2*)(g_outh  + (size_t)d * 64 + c0);

    for (int base = 0; base < cnt; base += 32) {
        int m = cnt - base; if (m > 32) m = 32;
        int myS = (lane < m) ? g_srcs[start + base + lane] : 0;  // coalesced
        int j = 0;
        for (; j + 4 <= m; j += 4) {
            int s0 = __shfl_sync(~0u, myS, j + 0);
            int s1 = __shfl_sync(~0u, myS, j + 1);
            int s2 = __shfl_sync(~0u, myS, j + 2);
            int s3 = __shfl_sync(~0u, myS, j + 3);
            float4 p0 = g_pos4[s0];
            float4 p1 = g_pos4[s1];
            float4 p2 = g_pos4[s2];
            float4 p3 = g_pos4[s3];
            uint2 u0 = *(const uint2*)(g_svh + (size_t)s0 * 128 + c0 * 2);
            uint2 u1 = *(const uint2*)(g_svh + (size_t)s1 * 128 + c0 * 2);
            uint2 u2 = *(const uint2*)(g_svh + (size_t)s2 * 128 + c0 * 2);
            uint2 u3 = *(const uint2*)(g_svh + (size_t)s3 * 128 + c0 * 2);
            edge_acc(pd, p0, u0, wx, wy, wz, bb, accD, accM);
            edge_acc(pd, p1, u1, wx, wy, wz, bb, accD, accM);
            edge_acc(pd, p2, u2, wx, wy, wz, bb, accD, accM);
            edge_acc(pd, p3, u3, wx, wy, wz, bb, accD, accM);
        }
        for (; j < m; j++) {
            int s0 = __shfl_sync(~0u, myS, j);
            float4 p0 = g_pos4[s0];
            uint2 u0 = *(const uint2*)(g_svh + (size_t)s0 * 128 + c0 * 2);
            edge_acc(pd, p0, u0, wx, wy, wz, bb, accD, accM);
        }
    }

    *(float2*)(g_denom + (size_t)d * 64 + c0) = accD;
    *(float2*)(g_outh  + (size_t)d * 64 + c0) = accM;
}

// ---------------- MLP: t = outh/denom; y = relu(t@W1+b1)@W2+b2 ----------------
__global__ void __launch_bounds__(256) mlp_kernel(
        const float* __restrict__ W1,
        const float* __restrict__ b1,
        const float* __restrict__ W2,
        const float* __restrict__ b2,
        float* __restrict__ out, int N) {
    __shared__ float sW1[64 * 64];
    __shared__ float sW2[64 * 64];
    __shared__ float sx [64 * 68];
    int tid  = threadIdx.x;
    int base = blockIdx.x * 64;

    for (int g = tid; g < 4096; g += 256) { sW1[g] = W1[g]; sW2[g] = W2[g]; }

    for (int i = tid; i < 1024; i += 256) {
        int n = i >> 4, c4 = i & 15;
        int node = base + n;
        float4 o4 = make_float4(0.f, 0.f, 0.f, 0.f);
        float4 d4 = make_float4(1.f, 1.f, 1.f, 1.f);
        if (node < N) {
            o4 = ((const float4*)g_outh)[(size_t)node * 16 + c4];
            d4 = ((const float4*)g_denom)[(size_t)node * 16 + c4];
        }
        int c = c4 * 4;
        sx[(c + 0) * 68 + n] = o4.x / d4.x;
        sx[(c + 1) * 68 + n] = o4.y / d4.y;
        sx[(c + 2) * 68 + n] = o4.z / d4.z;
        sx[(c + 3) * 68 + n] = o4.w / d4.w;
    }
    __syncthreads();

    int cg = tid & 15, ng = tid >> 4;
    float4 bias = *(const float4*)(b1 + cg * 4);
    float4 acc[4];
#pragma unroll
    for (int i = 0; i < 4; i++) acc[i] = bias;

#pragma unroll 8
    for (int k = 0; k < 64; k++) {
        float4 w  = *(float4*)(sW1 + k * 64 + cg * 4);
        float4 xa = *(float4*)(sx + k * 68 + ng * 4);
        float xv[4] = {xa.x, xa.y, xa.z, xa.w};
#pragma unroll
        for (int i = 0; i < 4; i++) {
            acc[i].x += xv[i] * w.x;
            acc[i].y += xv[i] * w.y;
            acc[i].z += xv[i] * w.z;
            acc[i].w += xv[i] * w.w;
        }
    }
    __syncthreads();

#pragma unroll
    for (int i = 0; i < 4; i++) {
        int n = ng * 4 + i;
        sx[(cg * 4 + 0) * 68 + n] = fmaxf(acc[i].x, 0.f);
        sx[(cg * 4 + 1) * 68 + n] = fmaxf(acc[i].y, 0.f);
        sx[(cg * 4 + 2) * 68 + n] = fmaxf(acc[i].z, 0.f);
        sx[(cg * 4 + 3) * 68 + n] = fmaxf(acc[i].w, 0.f);
    }
    __syncthreads();

    float4 bias2 = *(const float4*)(b2 + cg * 4);
#pragma unroll
    for (int i = 0; i < 4; i++) acc[i] = bias2;

#pragma unroll 8
    for (int k = 0; k < 64; k++) {
        float4 w  = *(float4*)(sW2 + k * 64 + cg * 4);
        float4 xa = *(float4*)(sx + k * 68 + ng * 4);
        float xv[4] = {xa.x, xa.y, xa.z, xa.w};
#pragma unroll
        for (int i = 0; i < 4; i++) {
            acc[i].x += xv[i] * w.x;
            acc[i].y += xv[i] * w.y;
            acc[i].z += xv[i] * w.z;
            acc[i].w += xv[i] * w.w;
        }
    }
#pragma unroll
    for (int i = 0; i < 4; i++) {
        int node = base + ng * 4 + i;
        if (node < N)
            *(float4*)(out + (size_t)node * 64 + cg * 4) = acc[i];
    }
}

extern "C" void kernel_launch(void* const* d_in, const int* in_sizes, int n_in,
                              void* d_out, int out_size) {
    const float* x    = (const float*)d_in[0];
    const float* pos  = (const float*)d_in[1];
    const int*   ei   = (const int*)d_in[2];
    const float* Wl   = (const float*)d_in[3];
    const float* Wsrc = (const float*)d_in[4];
    // d_in[5] = W_dst  (unused: cancels exactly in the segment softmax)
    const float* Wpos = (const float*)d_in[6];
    const float* bpos = (const float*)d_in[7];
    const float* W1   = (const float*)d_in[8];
    const float* b1   = (const float*)d_in[9];
    const float* W2   = (const float*)d_in[10];
    const float* b2   = (const float*)d_in[11];
    float* out = (float*)d_out;

    int N  = in_sizes[0] / 64;
    int E  = in_sizes[2] / 2;

    int nodeBlocks = (N + 63) / 64;
    int histBlocks = (E + 1023) / 1024;
    proj_kernel<<<nodeBlocks + histBlocks, 256>>>(x, pos, ei, Wl, Wsrc, bpos,
                                                  N, E, nodeBlocks);

    alloc_kernel<<<(N + 1023) / 1024, 1024>>>(N);

    scatter_kernel<<<(E + 255) / 256, 256>>>(ei, E);

    aggregate_kernel<<<(N * 32 + 255) / 256, 256>>>(Wpos, bpos, N);

    mlp_kernel<<<(N + 63) / 64, 256>>>(W1, b1, W2, b2, out, N);
}